// round 1
// baseline (speedup 1.0000x reference)
#include <cuda_runtime.h>
#include <cstdint>

#define N_NODES 100000
#define D 256

// Scratch for support = X @ W  (102.4 MB, static device allocation — allowed)
__device__ float g_support[(size_t)N_NODES * D];

// ---------------------------------------------------------------------------
// Kernel 1: tiled fp32 GEMM  support[M,256] = X[M,256] @ W[256,256]
// 64x64 tile, BK=16, 256 threads, 4x4 accumulators per thread.
// ---------------------------------------------------------------------------
__global__ __launch_bounds__(256) void gemm_kernel(const float* __restrict__ A,
                                                   const float* __restrict__ B) {
    const int BM = 64, BN = 64, BK = 16;
    __shared__ float As[BK][BM];   // As[k][m]
    __shared__ float Bs[BK][BN];   // Bs[k][n]

    int tid = threadIdx.x;            // 0..255
    int tx  = tid & 15;               // 16 col-groups
    int ty  = tid >> 4;               // 16 row-groups
    int blockRow = blockIdx.y * BM;
    int blockCol = blockIdx.x * BN;

    float acc[4][4] = {};

    for (int k0 = 0; k0 < D; k0 += BK) {
        // Load A tile 64x16 (1024 elems, 4 per thread), store transposed.
        #pragma unroll
        for (int i = 0; i < 4; i++) {
            int idx = tid + i * 256;
            int r = idx >> 4;          // 0..63
            int c = idx & 15;          // 0..15
            int row = blockRow + r;
            As[c][r] = (row < N_NODES) ? A[(size_t)row * D + k0 + c] : 0.0f;
        }
        // Load B tile 16x64
        #pragma unroll
        for (int i = 0; i < 4; i++) {
            int idx = tid + i * 256;
            int r = idx >> 6;          // 0..15
            int c = idx & 63;          // 0..63
            Bs[r][c] = B[(size_t)(k0 + r) * D + blockCol + c];
        }
        __syncthreads();

        #pragma unroll
        for (int k = 0; k < BK; k++) {
            float4 av = *reinterpret_cast<const float4*>(&As[k][ty * 4]);
            float4 bv = *reinterpret_cast<const float4*>(&Bs[k][tx * 4]);
            float a[4] = {av.x, av.y, av.z, av.w};
            float b[4] = {bv.x, bv.y, bv.z, bv.w};
            #pragma unroll
            for (int i = 0; i < 4; i++)
                #pragma unroll
                for (int j = 0; j < 4; j++)
                    acc[i][j] += a[i] * b[j];
        }
        __syncthreads();
    }

    #pragma unroll
    for (int i = 0; i < 4; i++) {
        int row = blockRow + ty * 4 + i;
        if (row < N_NODES) {
            float4 v = make_float4(acc[i][0], acc[i][1], acc[i][2], acc[i][3]);
            *reinterpret_cast<float4*>(&g_support[(size_t)row * D + blockCol + tx * 4]) = v;
        }
    }
}

// ---------------------------------------------------------------------------
// Kernel 2: out[i, :] = bias[:]   (d_out is poisoned — must initialize)
// One float4 per thread, grid-stride not needed (exact sizing).
// ---------------------------------------------------------------------------
__global__ __launch_bounds__(256) void init_out_kernel(float* __restrict__ out,
                                                       const float* __restrict__ bias) {
    int i = blockIdx.x * blockDim.x + threadIdx.x;      // float4 index
    const int TOTAL4 = N_NODES * (D / 4);               // 6.4M
    if (i < TOTAL4) {
        float4 b = *reinterpret_cast<const float4*>(bias + (i & 63) * 4);
        reinterpret_cast<float4*>(out)[i] = b;
    }
}

// ---------------------------------------------------------------------------
// Kernel 3: edge scatter. One warp per edge; lane handles 8 floats (2 float4).
// Uses vectorized L2 reduction red.global.add.v4.f32 (sm_90+): no return trip,
// 4x fewer red ops than scalar atomicAdd.
// ---------------------------------------------------------------------------
__global__ __launch_bounds__(256) void scatter_kernel(const int* __restrict__ adj_row,
                                                      const int* __restrict__ adj_col,
                                                      const float* __restrict__ adj_val,
                                                      float* __restrict__ out,
                                                      int nE) {
    int gtid = blockIdx.x * blockDim.x + threadIdx.x;
    int e    = gtid >> 5;       // warp id = edge id
    int lane = gtid & 31;
    if (e >= nE) return;

    int   r = adj_row[e];       // warp-uniform loads → single broadcast LDG
    int   c = adj_col[e];
    float v = adj_val[e];

    const float4* src = reinterpret_cast<const float4*>(g_support + (size_t)c * D) + lane * 2;
    float*        dst = out + (size_t)r * D + lane * 8;

    float4 s0 = src[0];
    float4 s1 = src[1];

    asm volatile("red.global.add.v4.f32 [%0], {%1,%2,%3,%4};"
                 :: "l"(dst), "f"(s0.x * v), "f"(s0.y * v), "f"(s0.z * v), "f"(s0.w * v)
                 : "memory");
    asm volatile("red.global.add.v4.f32 [%0], {%1,%2,%3,%4};"
                 :: "l"(dst + 4), "f"(s1.x * v), "f"(s1.y * v), "f"(s1.z * v), "f"(s1.w * v)
                 : "memory");
}

// ---------------------------------------------------------------------------
// Launch
// ---------------------------------------------------------------------------
extern "C" void kernel_launch(void* const* d_in, const int* in_sizes, int n_in,
                              void* d_out, int out_size) {
    const float* X    = (const float*)d_in[0];   // [100000, 256]
    const int*   arow = (const int*)  d_in[1];   // [E]
    const int*   acol = (const int*)  d_in[2];   // [E]
    const float* aval = (const float*)d_in[3];   // [E]
    const float* W    = (const float*)d_in[4];   // [256, 256]
    const float* bias = (const float*)d_in[5];   // [256]
    float*       out  = (float*)d_out;           // [100000, 256]

    int nE = in_sizes[1];

    // 1) support = X @ W
    dim3 gemm_grid(D / 64, (N_NODES + 63) / 64);
    gemm_kernel<<<gemm_grid, 256>>>(X, W);

    // 2) out = bias (broadcast)
    int total4 = N_NODES * (D / 4);
    init_out_kernel<<<(total4 + 255) / 256, 256>>>(out, bias);

    // 3) scatter-add edges
    long long total_threads = (long long)nE * 32;
    int nblk = (int)((total_threads + 255) / 256);
    scatter_kernel<<<nblk, 256>>>(arow, acol, aval, out, nE);
}

// round 2
// speedup vs baseline: 2.0733x; 2.0733x over previous
#include <cuda_runtime.h>
#include <cstdint>

#define N_NODES 100000
#define D 256
#define MAX_E 3200000

// Static device scratch (allocation-free rule)
__device__ float g_support[(size_t)N_NODES * D];   // X @ W         (102.4 MB)
__device__ int   g_count [N_NODES];
__device__ int   g_offset[N_NODES];                // CSR row start
__device__ int   g_cursor[N_NODES];
__device__ int   g_csr_col[MAX_E];
__device__ float g_csr_val[MAX_E];

// ---------------------------------------------------------------------------
// Kernel 1: SGEMM  support = X[100000,256] @ W[256,256]
// 128x128 tile, BK=8, 256 threads, 8x8 per thread (2x2 groups of 4x4).
// ---------------------------------------------------------------------------
__global__ __launch_bounds__(256) void gemm_kernel(const float* __restrict__ A,
                                                   const float* __restrict__ B) {
    const int BM = 128, BN = 128, BK = 8;
    __shared__ float As[BK][BM + 4];   // padded: conflict-free transposed stores
    __shared__ float Bs[BK][BN];

    int tid = threadIdx.x;
    int tx  = tid & 15;                // 0..15 -> col groups
    int ty  = tid >> 4;                // 0..15 -> row groups
    int blockRow = blockIdx.y * BM;
    int blockCol = blockIdx.x * BN;

    // A load mapping: one float4 per thread: row = tid/2, cols = (tid&1)*4..+3
    int a_r = tid >> 1;
    int a_c = (tid & 1) * 4;
    // B load mapping: row = tid/32, cols = (tid&31)*4
    int b_r = tid >> 5;
    int b_c = (tid & 31) * 4;

    float acc[2][2][4][4] = {};

    for (int k0 = 0; k0 < D; k0 += BK) {
        // A tile 128x8, transposed store
        {
            int row = blockRow + a_r;
            float4 v = make_float4(0.f, 0.f, 0.f, 0.f);
            if (row < N_NODES)
                v = *reinterpret_cast<const float4*>(&A[(size_t)row * D + k0 + a_c]);
            As[a_c + 0][a_r] = v.x;
            As[a_c + 1][a_r] = v.y;
            As[a_c + 2][a_r] = v.z;
            As[a_c + 3][a_r] = v.w;
        }
        // B tile 8x128
        {
            float4 v = *reinterpret_cast<const float4*>(&B[(size_t)(k0 + b_r) * D + blockCol + b_c]);
            *reinterpret_cast<float4*>(&Bs[b_r][b_c]) = v;
        }
        __syncthreads();

        #pragma unroll
        for (int k = 0; k < BK; k++) {
            float4 a0 = *reinterpret_cast<const float4*>(&As[k][ty * 4]);
            float4 a1 = *reinterpret_cast<const float4*>(&As[k][ty * 4 + 64]);
            float4 b0 = *reinterpret_cast<const float4*>(&Bs[k][tx * 4]);
            float4 b1 = *reinterpret_cast<const float4*>(&Bs[k][tx * 4 + 64]);
            float a[2][4] = {{a0.x, a0.y, a0.z, a0.w}, {a1.x, a1.y, a1.z, a1.w}};
            float b[2][4] = {{b0.x, b0.y, b0.z, b0.w}, {b1.x, b1.y, b1.z, b1.w}};
            #pragma unroll
            for (int ia = 0; ia < 2; ia++)
                #pragma unroll
                for (int ib = 0; ib < 2; ib++)
                    #pragma unroll
                    for (int i = 0; i < 4; i++)
                        #pragma unroll
                        for (int j = 0; j < 4; j++)
                            acc[ia][ib][i][j] += a[ia][i] * b[ib][j];
        }
        __syncthreads();
    }

    #pragma unroll
    for (int ia = 0; ia < 2; ia++) {
        #pragma unroll
        for (int i = 0; i < 4; i++) {
            int row = blockRow + ia * 64 + ty * 4 + i;
            if (row >= N_NODES) continue;
            #pragma unroll
            for (int ib = 0; ib < 2; ib++) {
                int col = blockCol + ib * 64 + tx * 4;
                float4 v = make_float4(acc[ia][ib][i][0], acc[ia][ib][i][1],
                                       acc[ia][ib][i][2], acc[ia][ib][i][3]);
                *reinterpret_cast<float4*>(&g_support[(size_t)row * D + col]) = v;
            }
        }
    }
}

// ---------------------------------------------------------------------------
// CSR construction: zero counts -> histogram -> scan -> scatter col/val
// ---------------------------------------------------------------------------
__global__ __launch_bounds__(256) void zero_count_kernel() {
    int i = blockIdx.x * blockDim.x + threadIdx.x;
    if (i < N_NODES) g_count[i] = 0;
}

__global__ __launch_bounds__(256) void hist_kernel(const int* __restrict__ adj_row, int nE) {
    int e = blockIdx.x * blockDim.x + threadIdx.x;
    if (e < nE) atomicAdd(&g_count[adj_row[e]], 1);
}

// Single-block exclusive scan of g_count -> g_offset (and g_cursor copy).
__global__ __launch_bounds__(1024) void scan_kernel() {
    __shared__ int partial[1024];
    int t = threadIdx.x;
    const int CHUNK = (N_NODES + 1023) / 1024;    // 98
    int start = t * CHUNK;
    int end   = min(start + CHUNK, N_NODES);

    int s = 0;
    for (int i = start; i < end; i++) s += g_count[i];
    partial[t] = s;
    __syncthreads();

    // Hillis-Steele inclusive scan
    for (int off = 1; off < 1024; off <<= 1) {
        int v = (t >= off) ? partial[t - off] : 0;
        __syncthreads();
        partial[t] += v;
        __syncthreads();
    }

    int run = (t == 0) ? 0 : partial[t - 1];
    for (int i = start; i < end; i++) {
        int c = g_count[i];
        g_offset[i] = run;
        g_cursor[i] = run;
        run += c;
    }
}

__global__ __launch_bounds__(256) void build_kernel(const int* __restrict__ adj_row,
                                                    const int* __restrict__ adj_col,
                                                    const float* __restrict__ adj_val,
                                                    int nE) {
    int e = blockIdx.x * blockDim.x + threadIdx.x;
    if (e >= nE) return;
    int r = adj_row[e];
    int pos = atomicAdd(&g_cursor[r], 1);
    g_csr_col[pos] = adj_col[e];
    g_csr_val[pos] = adj_val[e];
}

// ---------------------------------------------------------------------------
// Kernel: CSR SpMM. One warp per row; lane owns 8 floats (2 float4).
// Register accumulation over the row's edges; single store with bias fused.
// ---------------------------------------------------------------------------
__global__ __launch_bounds__(256) void spmm_kernel(const float* __restrict__ bias,
                                                   float* __restrict__ out) {
    int gtid = blockIdx.x * blockDim.x + threadIdx.x;
    int r    = gtid >> 5;
    int lane = gtid & 31;
    if (r >= N_NODES) return;

    int start = g_offset[r];
    int end   = start + g_count[r];

    float4 acc0 = make_float4(0.f, 0.f, 0.f, 0.f);
    float4 acc1 = make_float4(0.f, 0.f, 0.f, 0.f);

    int p = start;
    // 2x unrolled for memory-level parallelism
    for (; p + 1 < end; p += 2) {
        int   c0 = g_csr_col[p];
        float v0 = g_csr_val[p];
        int   c1 = g_csr_col[p + 1];
        float v1 = g_csr_val[p + 1];
        const float4* s0 = reinterpret_cast<const float4*>(g_support + (size_t)c0 * D) + lane * 2;
        const float4* s1 = reinterpret_cast<const float4*>(g_support + (size_t)c1 * D) + lane * 2;
        float4 x00 = s0[0], x01 = s0[1];
        float4 x10 = s1[0], x11 = s1[1];
        acc0.x += x00.x * v0; acc0.y += x00.y * v0; acc0.z += x00.z * v0; acc0.w += x00.w * v0;
        acc1.x += x01.x * v0; acc1.y += x01.y * v0; acc1.z += x01.z * v0; acc1.w += x01.w * v0;
        acc0.x += x10.x * v1; acc0.y += x10.y * v1; acc0.z += x10.z * v1; acc0.w += x10.w * v1;
        acc1.x += x11.x * v1; acc1.y += x11.y * v1; acc1.z += x11.z * v1; acc1.w += x11.w * v1;
    }
    if (p < end) {
        int   c = g_csr_col[p];
        float v = g_csr_val[p];
        const float4* s = reinterpret_cast<const float4*>(g_support + (size_t)c * D) + lane * 2;
        float4 x0 = s[0], x1 = s[1];
        acc0.x += x0.x * v; acc0.y += x0.y * v; acc0.z += x0.z * v; acc0.w += x0.w * v;
        acc1.x += x1.x * v; acc1.y += x1.y * v; acc1.z += x1.z * v; acc1.w += x1.w * v;
    }

    const float4* bp = reinterpret_cast<const float4*>(bias) + lane * 2;
    float4 b0 = bp[0], b1 = bp[1];
    acc0.x += b0.x; acc0.y += b0.y; acc0.z += b0.z; acc0.w += b0.w;
    acc1.x += b1.x; acc1.y += b1.y; acc1.z += b1.z; acc1.w += b1.w;

    float4* dst = reinterpret_cast<float4*>(out + (size_t)r * D) + lane * 2;
    dst[0] = acc0;
    dst[1] = acc1;
}

// ---------------------------------------------------------------------------
// Launch
// ---------------------------------------------------------------------------
extern "C" void kernel_launch(void* const* d_in, const int* in_sizes, int n_in,
                              void* d_out, int out_size) {
    const float* X    = (const float*)d_in[0];
    const int*   arow = (const int*)  d_in[1];
    const int*   acol = (const int*)  d_in[2];
    const float* aval = (const float*)d_in[3];
    const float* W    = (const float*)d_in[4];
    const float* bias = (const float*)d_in[5];
    float*       out  = (float*)d_out;

    int nE = in_sizes[1];
    if (nE > MAX_E) nE = MAX_E;

    // 1) support = X @ W
    dim3 gemm_grid(D / 128, (N_NODES + 127) / 128);
    gemm_kernel<<<gemm_grid, 256>>>(X, W);

    // 2) CSR build
    zero_count_kernel<<<(N_NODES + 255) / 256, 256>>>();
    hist_kernel<<<(nE + 255) / 256, 256>>>(arow, nE);
    scan_kernel<<<1, 1024>>>();
    build_kernel<<<(nE + 255) / 256, 256>>>(arow, acol, aval, nE);

    // 3) SpMM (warp per row), bias fused
    long long total_threads = (long long)N_NODES * 32;
    int nblk = (int)((total_threads + 255) / 256);
    spmm_kernel<<<nblk, 256>>>(bias, out);
}

// round 3
// speedup vs baseline: 2.7045x; 1.3044x over previous
#include <cuda_runtime.h>
#include <cstdint>

#define N_NODES 100000
#define D 256
#define MAX_E 3200000

#define SCAN_CHUNK 4096
#define SCAN_BLOCKS ((N_NODES + SCAN_CHUNK - 1) / SCAN_CHUNK)   // 25

// Static device scratch (allocation-free rule)
__device__ float g_support[(size_t)N_NODES * D];   // X @ W  (102.4 MB)
__device__ int   g_count [N_NODES];
__device__ int   g_offset[N_NODES];
__device__ int   g_cursor[N_NODES];
__device__ int   g_bsum  [SCAN_BLOCKS];
__device__ uint2 g_csr   [MAX_E];                  // {col, val bits}

// ---------------------------------------------------------------------------
// Kernel 1: SGEMM  support = X[100000,256] @ W[256,256]
// 128x128 tile, BK=16, 256 threads, 8x8 per thread (2x2 groups of 4x4).
// ---------------------------------------------------------------------------
__global__ __launch_bounds__(256) void gemm_kernel(const float* __restrict__ A,
                                                   const float* __restrict__ B) {
    const int BM = 128, BK = 16;
    __shared__ float As[BK][BM + 4];
    __shared__ float Bs[BK][128];

    int tid = threadIdx.x;
    int tx  = tid & 15;
    int ty  = tid >> 4;
    int blockRow = blockIdx.y * BM;
    int blockCol = blockIdx.x * 128;

    float acc[2][2][4][4] = {};

    for (int k0 = 0; k0 < D; k0 += BK) {
        // A tile 128x16 = 512 float4, 2 per thread (transposed store)
        #pragma unroll
        for (int i = 0; i < 2; i++) {
            int f = tid + i * 256;           // 0..511
            int r = f >> 2;                  // 0..127
            int c = (f & 3) * 4;             // 0,4,8,12
            int row = blockRow + r;
            float4 v = make_float4(0.f, 0.f, 0.f, 0.f);
            if (row < N_NODES)
                v = *reinterpret_cast<const float4*>(&A[(size_t)row * D + k0 + c]);
            As[c + 0][r] = v.x;
            As[c + 1][r] = v.y;
            As[c + 2][r] = v.z;
            As[c + 3][r] = v.w;
        }
        // B tile 16x128 = 512 float4, 2 per thread
        #pragma unroll
        for (int i = 0; i < 2; i++) {
            int f = tid + i * 256;
            int r = f >> 5;                  // 0..15
            int c = (f & 31) * 4;            // 0..124
            *reinterpret_cast<float4*>(&Bs[r][c]) =
                *reinterpret_cast<const float4*>(&B[(size_t)(k0 + r) * D + blockCol + c]);
        }
        __syncthreads();

        #pragma unroll
        for (int k = 0; k < BK; k++) {
            float4 a0 = *reinterpret_cast<const float4*>(&As[k][ty * 4]);
            float4 a1 = *reinterpret_cast<const float4*>(&As[k][ty * 4 + 64]);
            float4 b0 = *reinterpret_cast<const float4*>(&Bs[k][tx * 4]);
            float4 b1 = *reinterpret_cast<const float4*>(&Bs[k][tx * 4 + 64]);
            float a[2][4] = {{a0.x, a0.y, a0.z, a0.w}, {a1.x, a1.y, a1.z, a1.w}};
            float b[2][4] = {{b0.x, b0.y, b0.z, b0.w}, {b1.x, b1.y, b1.z, b1.w}};
            #pragma unroll
            for (int ia = 0; ia < 2; ia++)
                #pragma unroll
                for (int ib = 0; ib < 2; ib++)
                    #pragma unroll
                    for (int i = 0; i < 4; i++)
                        #pragma unroll
                        for (int j = 0; j < 4; j++)
                            acc[ia][ib][i][j] += a[ia][i] * b[ib][j];
        }
        __syncthreads();
    }

    #pragma unroll
    for (int ia = 0; ia < 2; ia++) {
        #pragma unroll
        for (int i = 0; i < 4; i++) {
            int row = blockRow + ia * 64 + ty * 4 + i;
            if (row >= N_NODES) continue;
            #pragma unroll
            for (int ib = 0; ib < 2; ib++) {
                int col = blockCol + ib * 64 + tx * 4;
                float4 v = make_float4(acc[ia][ib][i][0], acc[ia][ib][i][1],
                                       acc[ia][ib][i][2], acc[ia][ib][i][3]);
                *reinterpret_cast<float4*>(&g_support[(size_t)row * D + col]) = v;
            }
        }
    }
}

// ---------------------------------------------------------------------------
// CSR construction
// ---------------------------------------------------------------------------
__global__ __launch_bounds__(256) void zero_count_kernel() {
    int i = blockIdx.x * blockDim.x + threadIdx.x;
    if (i < N_NODES) g_count[i] = 0;
}

__global__ __launch_bounds__(256) void hist_kernel(const int* __restrict__ adj_row, int nE) {
    int e = blockIdx.x * blockDim.x + threadIdx.x;
    if (e < nE) atomicAdd(&g_count[adj_row[e]], 1);
}

// Scan stage 1: per-block local exclusive scan of 4096 counts (4/thread).
__global__ __launch_bounds__(1024) void scan1_kernel() {
    __shared__ int sh[1024];
    int b = blockIdx.x, t = threadIdx.x;
    int base = b * SCAN_CHUNK + t * 4;

    int c[4];
    #pragma unroll
    for (int i = 0; i < 4; i++)
        c[i] = (base + i < N_NODES) ? g_count[base + i] : 0;
    int s = c[0] + c[1] + c[2] + c[3];

    sh[t] = s;
    __syncthreads();
    #pragma unroll
    for (int off = 1; off < 1024; off <<= 1) {
        int v = (t >= off) ? sh[t - off] : 0;
        __syncthreads();
        sh[t] += v;
        __syncthreads();
    }

    int run = (t == 0) ? 0 : sh[t - 1];
    #pragma unroll
    for (int i = 0; i < 4; i++) {
        if (base + i < N_NODES) g_offset[base + i] = run;
        run += c[i];
    }
    if (t == 1023) g_bsum[b] = sh[1023];
}

// Scan stage 2: each block adds the prefix of preceding block sums.
__global__ __launch_bounds__(1024) void scan2_kernel() {
    __shared__ int s_pre;
    int b = blockIdx.x, t = threadIdx.x;

    if (t < 32) {
        int s = 0;
        for (int i = t; i < b; i += 32) s += g_bsum[i];
        #pragma unroll
        for (int o = 16; o > 0; o >>= 1)
            s += __shfl_down_sync(0xFFFFFFFF, s, o);
        if (t == 0) s_pre = s;
    }
    __syncthreads();
    int pre = s_pre;

    int base = b * SCAN_CHUNK + t * 4;
    #pragma unroll
    for (int i = 0; i < 4; i++) {
        int idx = base + i;
        if (idx < N_NODES) {
            int off = g_offset[idx] + pre;
            g_offset[idx] = off;
            g_cursor[idx] = off;
        }
    }
}

__global__ __launch_bounds__(256) void build_kernel(const int* __restrict__ adj_row,
                                                    const int* __restrict__ adj_col,
                                                    const float* __restrict__ adj_val,
                                                    int nE) {
    int e = blockIdx.x * blockDim.x + threadIdx.x;
    if (e >= nE) return;
    int r = adj_row[e];
    int pos = atomicAdd(&g_cursor[r], 1);
    g_csr[pos] = make_uint2((unsigned)adj_col[e], __float_as_uint(adj_val[e]));
}

// ---------------------------------------------------------------------------
// CSR SpMM: warp per row, lane owns 8 floats, 4x unrolled gather, bias fused.
// ---------------------------------------------------------------------------
__global__ __launch_bounds__(256) void spmm_kernel(const float* __restrict__ bias,
                                                   float* __restrict__ out) {
    int gtid = blockIdx.x * blockDim.x + threadIdx.x;
    int r    = gtid >> 5;
    int lane = gtid & 31;
    if (r >= N_NODES) return;

    int start = g_offset[r];
    int end   = start + g_count[r];

    float4 acc0 = make_float4(0.f, 0.f, 0.f, 0.f);
    float4 acc1 = make_float4(0.f, 0.f, 0.f, 0.f);

    int p = start;
    for (; p + 3 < end; p += 4) {
        uint2 e0 = g_csr[p + 0];
        uint2 e1 = g_csr[p + 1];
        uint2 e2 = g_csr[p + 2];
        uint2 e3 = g_csr[p + 3];
        const float4* s0 = reinterpret_cast<const float4*>(g_support + (size_t)e0.x * D) + lane * 2;
        const float4* s1 = reinterpret_cast<const float4*>(g_support + (size_t)e1.x * D) + lane * 2;
        const float4* s2 = reinterpret_cast<const float4*>(g_support + (size_t)e2.x * D) + lane * 2;
        const float4* s3 = reinterpret_cast<const float4*>(g_support + (size_t)e3.x * D) + lane * 2;
        float4 x00 = s0[0], x01 = s0[1];
        float4 x10 = s1[0], x11 = s1[1];
        float4 x20 = s2[0], x21 = s2[1];
        float4 x30 = s3[0], x31 = s3[1];
        float v0 = __uint_as_float(e0.y);
        float v1 = __uint_as_float(e1.y);
        float v2 = __uint_as_float(e2.y);
        float v3 = __uint_as_float(e3.y);
        acc0.x += x00.x * v0; acc0.y += x00.y * v0; acc0.z += x00.z * v0; acc0.w += x00.w * v0;
        acc1.x += x01.x * v0; acc1.y += x01.y * v0; acc1.z += x01.z * v0; acc1.w += x01.w * v0;
        acc0.x += x10.x * v1; acc0.y += x10.y * v1; acc0.z += x10.z * v1; acc0.w += x10.w * v1;
        acc1.x += x11.x * v1; acc1.y += x11.y * v1; acc1.z += x11.z * v1; acc1.w += x11.w * v1;
        acc0.x += x20.x * v2; acc0.y += x20.y * v2; acc0.z += x20.z * v2; acc0.w += x20.w * v2;
        acc1.x += x21.x * v2; acc1.y += x21.y * v2; acc1.z += x21.z * v2; acc1.w += x21.w * v2;
        acc0.x += x30.x * v3; acc0.y += x30.y * v3; acc0.z += x30.z * v3; acc0.w += x30.w * v3;
        acc1.x += x31.x * v3; acc1.y += x31.y * v3; acc1.z += x31.z * v3; acc1.w += x31.w * v3;
    }
    for (; p < end; p++) {
        uint2 e = g_csr[p];
        float v = __uint_as_float(e.y);
        const float4* s = reinterpret_cast<const float4*>(g_support + (size_t)e.x * D) + lane * 2;
        float4 x0 = s[0], x1 = s[1];
        acc0.x += x0.x * v; acc0.y += x0.y * v; acc0.z += x0.z * v; acc0.w += x0.w * v;
        acc1.x += x1.x * v; acc1.y += x1.y * v; acc1.z += x1.z * v; acc1.w += x1.w * v;
    }

    const float4* bp = reinterpret_cast<const float4*>(bias) + lane * 2;
    float4 b0 = bp[0], b1 = bp[1];
    acc0.x += b0.x; acc0.y += b0.y; acc0.z += b0.z; acc0.w += b0.w;
    acc1.x += b1.x; acc1.y += b1.y; acc1.z += b1.z; acc1.w += b1.w;

    float4* dst = reinterpret_cast<float4*>(out + (size_t)r * D) + lane * 2;
    dst[0] = acc0;
    dst[1] = acc1;
}

// ---------------------------------------------------------------------------
// Launch
// ---------------------------------------------------------------------------
extern "C" void kernel_launch(void* const* d_in, const int* in_sizes, int n_in,
                              void* d_out, int out_size) {
    const float* X    = (const float*)d_in[0];
    const int*   arow = (const int*)  d_in[1];
    const int*   acol = (const int*)  d_in[2];
    const float* aval = (const float*)d_in[3];
    const float* W    = (const float*)d_in[4];
    const float* bias = (const float*)d_in[5];
    float*       out  = (float*)d_out;

    int nE = in_sizes[1];
    if (nE > MAX_E) nE = MAX_E;

    // 1) support = X @ W
    dim3 gemm_grid(D / 128, (N_NODES + 127) / 128);
    gemm_kernel<<<gemm_grid, 256>>>(X, W);

    // 2) CSR build (parallel scan)
    zero_count_kernel<<<(N_NODES + 255) / 256, 256>>>();
    hist_kernel<<<(nE + 255) / 256, 256>>>(arow, nE);
    scan1_kernel<<<SCAN_BLOCKS, 1024>>>();
    scan2_kernel<<<SCAN_BLOCKS, 1024>>>();
    build_kernel<<<(nE + 255) / 256, 256>>>(arow, acol, aval, nE);

    // 3) SpMM (warp per row), bias fused
    long long total_threads = (long long)N_NODES * 32;
    int nblk = (int)((total_threads + 255) / 256);
    spmm_kernel<<<nblk, 256>>>(bias, out);
}